// round 13
// baseline (speedup 1.0000x reference)
#include <cuda_runtime.h>
#include <cuda_bf16.h>
#include <cuda_fp16.h>
#include <math.h>
#include <stdint.h>

#define B_ 32
#define T_ 512
#define D_ 1024
#define H_ 1024
#define ZN 4096
#define NBLK 128
#define NT2 512
#define RED_S 40

// ---------------- device scratch ----------------
__device__ unsigned g_xp[(size_t)T_ * 16384];   // 32MB: x (reversed time), fp16, mma-fragment packed per t
__device__ unsigned g_h16[2][16384];            // 128KB: double-buffered h, fp16, fragment packed
__device__ unsigned g_flags[NBLK * 32];         // per-block progress flags, 128B apart
__device__ unsigned g_done = 0;

// ---------------- helpers ----------------
__device__ __forceinline__ float sigf(float x) { return 1.0f / (1.0f + __expf(-x)); }

__device__ __forceinline__ uint32_t packh2(float a, float b) {
    __half2 h = __halves2half2(__float2half_rn(a), __float2half_rn(b));
    return *(uint32_t*)&h;
}

// fp16 mma m16n8k16, fp32 accumulate
__device__ __forceinline__ void mma_f16(float* c, const uint32_t* a, uint32_t b0, uint32_t b1) {
    asm volatile(
        "mma.sync.aligned.m16n8k16.row.col.f32.f16.f16.f32 "
        "{%0,%1,%2,%3}, {%4,%5,%6,%7}, {%8,%9}, {%0,%1,%2,%3};"
        : "+f"(c[0]), "+f"(c[1]), "+f"(c[2]), "+f"(c[3])
        : "r"(a[0]), "r"(a[1]), "r"(a[2]), "r"(a[3]), "r"(b0), "r"(b1));
}

__device__ __forceinline__ unsigned ld_acq(const unsigned* p) {
    unsigned v;
    asm volatile("ld.global.acquire.gpu.u32 %0, [%1];" : "=r"(v) : "l"(p) : "memory");
    return v;
}
__device__ __forceinline__ void st_rel(unsigned* p, unsigned v) {
    asm volatile("st.global.release.gpu.u32 [%0], %1;" :: "l"(p), "r"(v) : "memory");
}

// fragment word index for element (b, k) in a 32x1024 fp16 operand (R11/R12-verified layout)
// word(b,k) = ((k>>4)*2 + (b>>4))*128 + ((b&7)*4 + ((k&7)>>1))*4 + ((k>>3)&1)*2 + ((b>>3)&1)

// ========== Repack x into per-t fragment layout: g_xp[t*16384 + word(b,k)] ==========
__global__ __launch_bounds__(256) void repack_x(const float* __restrict__ x) {
    const int t = blockIdx.x;            // 0..511 (processing order; source time T-1-t)
    const int tid = threadIdx.x;
    const int b = tid >> 3;              // 0..31
    const int k0 = (tid & 7) * 128;      // k range [k0, k0+128)

    const float* src = x + ((size_t)b * T_ + (size_t)(T_ - 1 - t)) * D_ + k0;
    unsigned* dst = g_xp + (size_t)t * 16384;
    const int bhi = ((b >> 4) & 1) * 128;
    const int bmid = (b & 7) * 16;
    const int blo = (b >> 3) & 1;

#pragma unroll 8
    for (int j = 0; j < 64; ++j) {
        int k = k0 + 2 * j;
        float2 v = *(const float2*)(src + 2 * j);
        int word = (k >> 4) * 256 + bhi + bmid + ((k & 7) >> 1) * 4 + ((k >> 3) & 1) * 2 + blo;
        dst[word] = packh2(v.x, v.y);
    }
}

// ---- shared mma+STS body: warp computes its 32x32 z-partial over its 128-k slice ----
__device__ __forceinline__ void mma_sts(const uint4* __restrict__ abase,
                                        const uint4* __restrict__ Wq,
                                        float* __restrict__ red,
                                        int wid, int lane, int g4, int l4) {
    float acc[2][4][4];
#pragma unroll
    for (int mt = 0; mt < 2; ++mt)
#pragma unroll
        for (int nt = 0; nt < 4; ++nt)
#pragma unroll
            for (int e = 0; e < 4; ++e) acc[mt][nt][e] = 0.0f;

#pragma unroll
    for (int kk = 0; kk < 8; ++kk) {
        int c16 = (wid & 7) * 8 + kk;
        uint4 b0 = Wq[kk * 64 + lane];
        uint4 b1 = Wq[kk * 64 + 32 + lane];
        uint32_t a[2][4];
#pragma unroll
        for (int mt = 0; mt < 2; ++mt) {
            uint4 v = __ldcg(&abase[(c16 * 2 + mt) * 32 + lane]);
            a[mt][0] = v.x; a[mt][1] = v.y; a[mt][2] = v.z; a[mt][3] = v.w;
        }
#pragma unroll
        for (int mt = 0; mt < 2; ++mt) {
            mma_f16(acc[mt][0], a[mt], b0.x, b0.y);
            mma_f16(acc[mt][1], a[mt], b0.z, b0.w);
            mma_f16(acc[mt][2], a[mt], b1.x, b1.y);
            mma_f16(acc[mt][3], a[mt], b1.z, b1.w);
        }
    }

#pragma unroll
    for (int mt = 0; mt < 2; ++mt) {
#pragma unroll
        for (int nt = 0; nt < 4; ++nt) {
            int row = mt * 16 + g4;
            int col = nt * 8 + 2 * l4;
            *(float2*)&red[wid * (32 * RED_S) + row * RED_S + col] =
                make_float2(acc[mt][nt][0], acc[mt][nt][1]);
            *(float2*)&red[wid * (32 * RED_S) + (row + 8) * RED_S + col] =
                make_float2(acc[mt][nt][2], acc[mt][nt][3]);
        }
    }
}

// ============ Fused persistent LSTM: z = [x_t, h] @ W + bias, 512 steps ===========
// 16 warps: 0-7 = x-warps (K rows [w*128,+128) of concat W = x part; also gate threads),
//           8-15 = h-warps (K rows 1024+(w-8)*128; poll 16 producer blocks each).
__global__ __launch_bounds__(NT2, 1) void lstm_fused(const float* __restrict__ Wfull,
                                                     const float* __restrict__ bias,
                                                     float* __restrict__ out) {
    extern __shared__ uint32_t dynsmem[];
    uint32_t* W_s = dynsmem;                         // 16 slabs * 2048 words = 128KB
    float* red = (float*)(dynsmem + 32768);          // 16 * 32 * 40 floats = 80KB

    const int tid = threadIdx.x;
    const int wid = tid >> 5, lane = tid & 31;
    const int l4 = lane & 3, g4 = lane >> 2;
    const int bid = blockIdx.x;
    const int n0 = bid * 8;
    const int pb = (tid >> 3) & 31;
    const int pn = tid & 7;
    const bool gate_role = tid < 256;    // x-warps double as gate threads

    // pointwise h-store address: element (b=pb, k=n0+pn), fragment layout
    const int hword = ((bid >> 1) * 2 + (pb >> 4)) * 128 + ((pb & 7) * 4 + (pn >> 1)) * 4 +
                      (bid & 1) * 2 + ((pb >> 3) & 1);
    const int hbyte = hword * 4 + (pn & 1) * 2;

    // ---- pack concat-W slice into SMEM (fp16, warp-centric) ----
    // slab w (2048 words) holds concat rows [w*128, w*128+128) for this block's 32 z-cols
    for (int widx = tid; widx < 32768; widx += NT2) {
        int w = widx >> 11, rem = widx & 2047;
        int kk = rem >> 8, q128 = (rem >> 7) & 1;
        int lw = (rem >> 2) & 31, low2 = rem & 3;
        int nt = q128 * 2 + (low2 >> 1), hi = low2 & 1;
        int g4c = lw >> 2, l4w = lw & 3;
        int k = w * 128 + kk * 16 + hi * 8 + l4w * 2;   // concat row (x: 0-1023, h: 1024-2047)
        int col = nt * H_ + n0 + g4c;
        W_s[widx] = packh2(__ldg(Wfull + (size_t)k * ZN + col),
                           __ldg(Wfull + (size_t)(k + 1) * ZN + col));
    }

    float bz[4];
    if (gate_role) {
#pragma unroll
        for (int g = 0; g < 4; ++g) bz[g] = __ldg(bias + g * H_ + n0 + pn);
    }
    __syncthreads();

    const uint4* Wq = (const uint4*)W_s + (size_t)wid * 512;
    float c_reg = 0.0f;

    // ---- prologue: step-0 partials (h = 0 -> h-warps contribute zeros) ----
    if (wid < 8) {
        mma_sts((const uint4*)g_xp, Wq, red, wid, lane, g4, l4);
    } else {
        for (int i = lane; i < 32 * RED_S; i += 32) red[wid * (32 * RED_S) + i] = 0.0f;
    }

    for (int t = 0; t < T_ - 1; ++t) {
        __syncthreads();   // sync#A: all partials for step t visible

        if (gate_role) {
            // ---- reduce 16 partials + bias -> gates -> c,h ----
            float z[4];
#pragma unroll
            for (int g = 0; g < 4; ++g) {
                float s = bz[g];
#pragma unroll
                for (int w = 0; w < 16; ++w)
                    s += red[w * (32 * RED_S) + pb * RED_S + g * 8 + pn];
                z[g] = s;
            }
            c_reg = sigf(z[2] + 1.0f) * c_reg + sigf(z[0]) * tanhf(z[1]);
            float hv = sigf(z[3]) * tanhf(c_reg);
            unsigned short hs = __half_as_ushort(__float2half_rn(hv));
            asm volatile("st.global.cg.u16 [%0], %1;"
                         :: "l"((char*)g_h16[(t + 1) & 1] + hbyte), "h"(hs) : "memory");
            asm volatile("bar.sync 2, 256;" ::: "memory");
            if (tid == 0) st_rel(&g_flags[bid * 32], (unsigned)(t + 1));
            __stcs(&out[(size_t)pb * (T_ * H_) + (size_t)t * H_ + n0 + pn], c_reg);
        } else {
            // ---- h-warps: poll producers for h(t+1), overlapped with gates ----
            if (lane < 16) {
                const unsigned* fp = &g_flags[((wid - 8) * 16 + lane) * 32];
                while (ld_acq(fp) < (unsigned)(t + 1)) { }
            }
            __syncwarp();
        }

        __syncthreads();   // sync#B: gates(t) done (red free), polls done

        if (gate_role) {
            // x projection for step t+1 (no cross-block dependency)
            mma_sts((const uint4*)(g_xp + (size_t)(t + 1) * 16384), Wq, red, wid, lane, g4, l4);
        } else {
            // recurrent part for step t+1
            mma_sts((const uint4*)g_h16[(t + 1) & 1], Wq, red, wid, lane, g4, l4);
        }
    }

    // ---- epilogue: finalize step T-1 ----
    __syncthreads();
    if (gate_role) {
        float z[4];
#pragma unroll
        for (int g = 0; g < 4; ++g) {
            float s = bz[g];
#pragma unroll
            for (int w = 0; w < 16; ++w)
                s += red[w * (32 * RED_S) + pb * RED_S + g * 8 + pn];
            z[g] = s;
        }
        c_reg = sigf(z[2] + 1.0f) * c_reg + sigf(z[0]) * tanhf(z[1]);
        __stcs(&out[(size_t)pb * (T_ * H_) + (size_t)(T_ - 1) * H_ + n0 + pn], c_reg);
    }

    // ---- reset flags for deterministic graph replay ----
    __syncthreads();
    if (tid == 0) atomicAdd(&g_done, 1u);
    if (bid == 0) {
        if (tid == 0) {
            while (*(volatile unsigned*)&g_done < (unsigned)NBLK) { }
        }
        __syncthreads();
        if (tid < NBLK) g_flags[tid * 32] = 0u;
        __syncthreads();
        if (tid == 0) { __threadfence(); g_done = 0u; }
    }
}

// ---------------- launch ----------------
extern "C" void kernel_launch(void* const* d_in, const int* in_sizes, int n_in,
                              void* d_out, int out_size) {
    (void)in_sizes; (void)n_in; (void)out_size;
    const float* x    = (const float*)d_in[0];
    const float* kern = (const float*)d_in[2];
    const float* bias = (const float*)d_in[3];
    float* out = (float*)d_out;

    const int smem2 = (32768 + 16 * 32 * RED_S) * 4;   // 212992 B
    cudaFuncSetAttribute(lstm_fused, cudaFuncAttributeMaxDynamicSharedMemorySize, smem2);

    repack_x<<<T_, 256>>>(x);
    lstm_fused<<<NBLK, NT2, smem2>>>(kern, bias, out);
}

// round 14
// speedup vs baseline: 1.2063x; 1.2063x over previous
#include <cuda_runtime.h>
#include <cuda_bf16.h>
#include <cuda_fp16.h>
#include <math.h>
#include <stdint.h>

#define B_ 32
#define T_ 512
#define D_ 1024
#define H_ 1024
#define ZN 4096
#define NBLK 128
#define NT2 512
#define RED_S 40

// ---------------- device scratch ----------------
__device__ unsigned g_xp[(size_t)T_ * 16384];   // 32MB: x (reversed time), fp16, mma-fragment packed per t
__device__ unsigned g_h16[2][16384];            // 128KB: double-buffered h, fp16, fragment packed
__device__ unsigned g_flags[NBLK * 32];         // per-block progress flags, 128B apart
__device__ unsigned g_done = 0;

// ---------------- helpers ----------------
__device__ __forceinline__ float sigf(float x) { return 1.0f / (1.0f + __expf(-x)); }

__device__ __forceinline__ uint32_t packh2(float a, float b) {
    __half2 h = __halves2half2(__float2half_rn(a), __float2half_rn(b));
    return *(uint32_t*)&h;
}

// fp16 mma m16n8k16, fp32 accumulate
__device__ __forceinline__ void mma_f16(float* c, const uint32_t* a, uint32_t b0, uint32_t b1) {
    asm volatile(
        "mma.sync.aligned.m16n8k16.row.col.f32.f16.f16.f32 "
        "{%0,%1,%2,%3}, {%4,%5,%6,%7}, {%8,%9}, {%0,%1,%2,%3};"
        : "+f"(c[0]), "+f"(c[1]), "+f"(c[2]), "+f"(c[3])
        : "r"(a[0]), "r"(a[1]), "r"(a[2]), "r"(a[3]), "r"(b0), "r"(b1));
}

__device__ __forceinline__ unsigned ld_acq(const unsigned* p) {
    unsigned v;
    asm volatile("ld.global.acquire.gpu.u32 %0, [%1];" : "=r"(v) : "l"(p) : "memory");
    return v;
}
__device__ __forceinline__ void st_rel(unsigned* p, unsigned v) {
    asm volatile("st.global.release.gpu.u32 [%0], %1;" :: "l"(p), "r"(v) : "memory");
}

// fragment word index for element (b, k) in a 32x1024 fp16 operand (R11-verified layout):
// word(b,k) = ((k>>4)*2 + (b>>4))*128 + ((b&7)*4 + ((k&7)>>1))*4 + ((k>>3)&1)*2 + ((b>>3)&1)

// ========== Repack x into per-t fragment layout: g_xp[t*16384 + word(b,k)] ==========
__global__ __launch_bounds__(256) void repack_x(const float* __restrict__ x) {
    const int t = blockIdx.x;            // processing order; source time T-1-t
    const int tid = threadIdx.x;
    const int b = tid >> 3;
    const int k0 = (tid & 7) * 128;

    const float* src = x + ((size_t)b * T_ + (size_t)(T_ - 1 - t)) * D_ + k0;
    unsigned* dst = g_xp + (size_t)t * 16384;
    const int bhi = ((b >> 4) & 1) * 128;
    const int bmid = (b & 7) * 16;
    const int blo = (b >> 3) & 1;

#pragma unroll 8
    for (int j = 0; j < 64; ++j) {
        int k = k0 + 2 * j;
        float2 v = *(const float2*)(src + 2 * j);
        int word = (k >> 4) * 256 + bhi + bmid + ((k & 7) >> 1) * 4 + ((k >> 3) & 1) * 2 + blo;
        dst[word] = packh2(v.x, v.y);
    }
}

// ---- mma + STS body: warp computes its 32x32 z-partial over its 128-k slice ----
__device__ __forceinline__ void mma_sts(const uint4* __restrict__ abase, int c16base,
                                        const uint4* __restrict__ Wq,
                                        float* __restrict__ red,
                                        int wid, int lane, int g4, int l4) {
    float acc[2][4][4];
#pragma unroll
    for (int mt = 0; mt < 2; ++mt)
#pragma unroll
        for (int nt = 0; nt < 4; ++nt)
#pragma unroll
            for (int e = 0; e < 4; ++e) acc[mt][nt][e] = 0.0f;

#pragma unroll
    for (int kk = 0; kk < 8; ++kk) {
        int c16 = c16base + kk;
        uint4 b0 = Wq[kk * 64 + lane];
        uint4 b1 = Wq[kk * 64 + 32 + lane];
        uint32_t a[2][4];
#pragma unroll
        for (int mt = 0; mt < 2; ++mt) {
            uint4 v = __ldcg(&abase[(c16 * 2 + mt) * 32 + lane]);
            a[mt][0] = v.x; a[mt][1] = v.y; a[mt][2] = v.z; a[mt][3] = v.w;
        }
#pragma unroll
        for (int mt = 0; mt < 2; ++mt) {
            mma_f16(acc[mt][0], a[mt], b0.x, b0.y);
            mma_f16(acc[mt][1], a[mt], b0.z, b0.w);
            mma_f16(acc[mt][2], a[mt], b1.x, b1.y);
            mma_f16(acc[mt][3], a[mt], b1.z, b1.w);
        }
    }

#pragma unroll
    for (int mt = 0; mt < 2; ++mt) {
#pragma unroll
        for (int nt = 0; nt < 4; ++nt) {
            int row = mt * 16 + g4;
            int col = nt * 8 + 2 * l4;
            *(float2*)&red[wid * (32 * RED_S) + row * RED_S + col] =
                make_float2(acc[mt][nt][0], acc[mt][nt][1]);
            *(float2*)&red[wid * (32 * RED_S) + (row + 8) * RED_S + col] =
                make_float2(acc[mt][nt][2], acc[mt][nt][3]);
        }
    }
}

// ============ Fused persistent LSTM, decoupled x-pipeline ===========
// h-warps 0-7 (critical path + gates): concat-W rows 1024+w*128.. (h part).
// x-warps 8-15 (free-running, 1 step ahead): concat-W rows (w-8)*128.. (x part),
// reduce their partials into the xz ring (parity slots) off the critical chain.
__global__ __launch_bounds__(NT2, 1) void lstm_fused(const float* __restrict__ Wfull,
                                                     const float* __restrict__ bias,
                                                     float* __restrict__ out) {
    extern __shared__ uint32_t dynsmem[];
    uint32_t* W_s = dynsmem;                          // 16 slabs * 2048 words = 128KB
    float* red = (float*)(dynsmem + 32768);           // 16 * 32 * 40 floats = 80KB
    float* xz = red + 16 * 32 * RED_S;                // 2 * 32*33 floats = 8.25KB

    const int tid = threadIdx.x;
    const int wid = tid >> 5, lane = tid & 31;
    const int l4 = lane & 3, g4 = lane >> 2;
    const int bid = blockIdx.x;
    const int n0 = bid * 8;
    const int pb = (tid >> 3) & 31;
    const int pn = tid & 7;
    const bool h_role = wid < 8;   // h-warps double as gate threads

    // pointwise h-store address: element (b=pb, k=n0+pn), fragment layout
    const int hword = ((bid >> 1) * 2 + (pb >> 4)) * 128 + ((pb & 7) * 4 + (pn >> 1)) * 4 +
                      (bid & 1) * 2 + ((pb >> 3) & 1);
    const int hbyte = hword * 4 + (pn & 1) * 2;

    // ---- pack concat-W slice into SMEM (fp16, warp-centric) ----
    // slab w: concat rows [base_k(w), +128): h-warps get the h part, x-warps the x part
    for (int widx = tid; widx < 32768; widx += NT2) {
        int w = widx >> 11, rem = widx & 2047;
        int kk = rem >> 8, q128 = (rem >> 7) & 1;
        int lw = (rem >> 2) & 31, low2 = rem & 3;
        int nt = q128 * 2 + (low2 >> 1), hi = low2 & 1;
        int g4c = lw >> 2, l4w = lw & 3;
        int kbase = (w < 8) ? (1024 + w * 128) : ((w - 8) * 128);
        int k = kbase + kk * 16 + hi * 8 + l4w * 2;
        int col = nt * H_ + n0 + g4c;
        W_s[widx] = packh2(__ldg(Wfull + (size_t)k * ZN + col),
                           __ldg(Wfull + (size_t)(k + 1) * ZN + col));
    }

    float bz[4];
    if (h_role) {
#pragma unroll
        for (int g = 0; g < 4; ++g) bz[g] = __ldg(bias + g * H_ + n0 + pn);
    }

    const uint4* Wq = (const uint4*)W_s + (size_t)wid * 512;
    float c_reg = 0.0f;

    // ---- prologue ----
    if (h_role) {
        // zero own h-partial slab (h(0) = 0)
        for (int i = lane; i < 32 * RED_S; i += 32) red[wid * (32 * RED_S) + i] = 0.0f;
        __syncthreads();   // W_s ready (x-warps need it below)... all sync once here
    } else {
        __syncthreads();   // W_s visible
        // compute xz[0]
        mma_sts((const uint4*)g_xp, (wid - 8) * 8, Wq, red, wid, lane, g4, l4);
        asm volatile("bar.sync 3, 256;" ::: "memory");
        int lt = tid - 256;
#pragma unroll
        for (int rep = 0; rep < 4; ++rep) {
            int o = lt + rep * 256;
            int b = o >> 5, cc = o & 31;
            float s = 0.0f;
#pragma unroll
            for (int w = 8; w < 16; ++w) s += red[w * (32 * RED_S) + b * RED_S + cc];
            xz[b * 33 + cc] = s;
        }
    }

    for (int t = 0; t < T_ - 1; ++t) {
        __syncthreads();   // sync#A(t): h partials(t), xz[t] visible

        if (h_role) {
            // ---- gates for step t ----
            float z[4];
#pragma unroll
            for (int g = 0; g < 4; ++g) {
                float s = bz[g] + xz[(t & 1) * 1056 + pb * 33 + g * 8 + pn];
#pragma unroll
                for (int w = 0; w < 8; ++w)
                    s += red[w * (32 * RED_S) + pb * RED_S + g * 8 + pn];
                z[g] = s;
            }
            c_reg = sigf(z[2] + 1.0f) * c_reg + sigf(z[0]) * tanhf(z[1]);
            float hv = sigf(z[3]) * tanhf(c_reg);
            unsigned short hs = __half_as_ushort(__float2half_rn(hv));
            asm volatile("st.global.cg.u16 [%0], %1;"
                         :: "l"((char*)g_h16[(t + 1) & 1] + hbyte), "h"(hs) : "memory");
            asm volatile("bar.sync 2, 256;" ::: "memory");   // gates-read + h-store done
            if (tid == 0) st_rel(&g_flags[bid * 32], (unsigned)(t + 1));
            __stcs(&out[(size_t)pb * (T_ * H_) + (size_t)t * H_ + n0 + pn], c_reg);

            // ---- poll own 16 producers for h(t+1), then recurrent mma ----
            if (lane < 16) {
                const unsigned* fp = &g_flags[(wid * 16 + lane) * 32];
                while (ld_acq(fp) < (unsigned)(t + 1)) { }
            }
            __syncwarp();
            mma_sts((const uint4*)g_h16[(t + 1) & 1], wid * 8, Wq, red, wid, lane, g4, l4);
        } else {
            // ---- x-pipeline: prefetch x(t+2), compute xz[t+1] ----
            if (t + 2 < T_) {
                const char* pf = (const char*)(g_xp + (size_t)(t + 2) * 16384 +
                                               (wid - 8) * 2048) + lane * 128;
                asm volatile("prefetch.global.L2 [%0];" :: "l"(pf));
                asm volatile("prefetch.global.L2 [%0];" :: "l"(pf + 4096));
            }
            mma_sts((const uint4*)(g_xp + (size_t)(t + 1) * 16384), (wid - 8) * 8,
                    Wq, red, wid, lane, g4, l4);
            asm volatile("bar.sync 3, 256;" ::: "memory");
            int lt = tid - 256;
#pragma unroll
            for (int rep = 0; rep < 4; ++rep) {
                int o = lt + rep * 256;
                int b = o >> 5, cc = o & 31;
                float s = 0.0f;
#pragma unroll
                for (int w = 8; w < 16; ++w) s += red[w * (32 * RED_S) + b * RED_S + cc];
                xz[((t + 1) & 1) * 1056 + b * 33 + cc] = s;
            }
        }
    }

    // ---- epilogue: gates for step T-1 ----
    __syncthreads();
    if (h_role) {
        float z[4];
#pragma unroll
        for (int g = 0; g < 4; ++g) {
            float s = bz[g] + xz[((T_ - 1) & 1) * 1056 + pb * 33 + g * 8 + pn];
#pragma unroll
            for (int w = 0; w < 8; ++w)
                s += red[w * (32 * RED_S) + pb * RED_S + g * 8 + pn];
            z[g] = s;
        }
        c_reg = sigf(z[2] + 1.0f) * c_reg + sigf(z[0]) * tanhf(z[1]);
        __stcs(&out[(size_t)pb * (T_ * H_) + (size_t)(T_ - 1) * H_ + n0 + pn], c_reg);
    }

    // ---- reset flags for deterministic graph replay ----
    __syncthreads();
    if (tid == 0) atomicAdd(&g_done, 1u);
    if (bid == 0) {
        if (tid == 0) {
            while (*(volatile unsigned*)&g_done < (unsigned)NBLK) { }
        }
        __syncthreads();
        if (tid < NBLK) g_flags[tid * 32] = 0u;
        __syncthreads();
        if (tid == 0) { __threadfence(); g_done = 0u; }
    }
}

// ---------------- launch ----------------
extern "C" void kernel_launch(void* const* d_in, const int* in_sizes, int n_in,
                              void* d_out, int out_size) {
    (void)in_sizes; (void)n_in; (void)out_size;
    const float* x    = (const float*)d_in[0];
    const float* kern = (const float*)d_in[2];
    const float* bias = (const float*)d_in[3];
    float* out = (float*)d_out;

    const int smem2 = (32768 + 16 * 32 * RED_S + 2 * 1056) * 4;   // 221440 B
    cudaFuncSetAttribute(lstm_fused, cudaFuncAttributeMaxDynamicSharedMemorySize, smem2);

    repack_x<<<T_, 256>>>(x);
    lstm_fused<<<NBLK, NT2, smem2>>>(kern, bias, out);
}

// round 15
// speedup vs baseline: 1.4715x; 1.2198x over previous
#include <cuda_runtime.h>
#include <cuda_bf16.h>
#include <cuda_fp16.h>
#include <math.h>
#include <stdint.h>

#define B_ 32
#define T_ 512
#define D_ 1024
#define H_ 1024
#define ZN 4096
#define NBLK 128
#define NT2 512
#define RED_S 40

// ---------------- device scratch ----------------
__device__ unsigned g_xp[(size_t)T_ * 16384];   // 32MB: x (reversed time), fp16, mma-fragment packed per t
__device__ unsigned g_h16[2][16384];            // 128KB: double-buffered h, fp16, fragment packed
__device__ unsigned g_flags[NBLK * 32];         // per-block progress flags, 128B apart
__device__ unsigned g_done = 0;

// ---------------- helpers ----------------
__device__ __forceinline__ float sigf(float x) { return 1.0f / (1.0f + __expf(-x)); }

__device__ __forceinline__ uint32_t packh2(float a, float b) {
    __half2 h = __halves2half2(__float2half_rn(a), __float2half_rn(b));
    return *(uint32_t*)&h;
}

// fp16 mma m16n8k16, fp32 accumulate
__device__ __forceinline__ void mma_f16(float* c, const uint32_t* a, uint32_t b0, uint32_t b1) {
    asm volatile(
        "mma.sync.aligned.m16n8k16.row.col.f32.f16.f16.f32 "
        "{%0,%1,%2,%3}, {%4,%5,%6,%7}, {%8,%9}, {%0,%1,%2,%3};"
        : "+f"(c[0]), "+f"(c[1]), "+f"(c[2]), "+f"(c[3])
        : "r"(a[0]), "r"(a[1]), "r"(a[2]), "r"(a[3]), "r"(b0), "r"(b1));
}

__device__ __forceinline__ unsigned ld_acq(const unsigned* p) {
    unsigned v;
    asm volatile("ld.global.acquire.gpu.u32 %0, [%1];" : "=r"(v) : "l"(p) : "memory");
    return v;
}
__device__ __forceinline__ void st_rel(unsigned* p, unsigned v) {
    asm volatile("st.global.release.gpu.u32 [%0], %1;" :: "l"(p), "r"(v) : "memory");
}

// fragment word(b,k) for a 32x1024 fp16 operand (verified R12-R14):
// ((k>>4)*2 + (b>>4))*128 + ((b&7)*4 + ((k&7)>>1))*4 + ((k>>3)&1)*2 + ((b>>3)&1)

// ========== Repack x into per-t fragment layout: g_xp[t*16384 + word(b,k)] ==========
__global__ __launch_bounds__(256) void repack_x(const float* __restrict__ x) {
    const int t = blockIdx.x;            // processing order; source time T-1-t
    const int tid = threadIdx.x;
    const int b = tid >> 3;
    const int k0 = (tid & 7) * 128;

    const float* src = x + ((size_t)b * T_ + (size_t)(T_ - 1 - t)) * D_ + k0;
    unsigned* dst = g_xp + (size_t)t * 16384;
    const int bhi = ((b >> 4) & 1) * 128;
    const int bmid = (b & 7) * 16;
    const int blo = (b >> 3) & 1;

#pragma unroll 8
    for (int j = 0; j < 64; ++j) {
        int k = k0 + 2 * j;
        float2 v = *(const float2*)(src + 2 * j);
        int word = (k >> 4) * 256 + bhi + bmid + ((k & 7) >> 1) * 4 + ((k >> 3) & 1) * 2 + blo;
        dst[word] = packh2(v.x, v.y);
    }
}

// ---- accumulate one 64-k operand slice into acc (4 c16 chunks, R12 shape) ----
__device__ __forceinline__ void mma_part(float* acc /*[2][4][4] flat*/,
                                         const uint4* __restrict__ abase,
                                         const uint4* __restrict__ Wq,
                                         int c16base, int lane) {
#pragma unroll
    for (int kk = 0; kk < 4; ++kk) {
        int c16 = c16base + kk;
        uint4 b0 = Wq[kk * 64 + lane];
        uint4 b1 = Wq[kk * 64 + 32 + lane];
        uint32_t a[2][4];
#pragma unroll
        for (int mt = 0; mt < 2; ++mt) {
            uint4 v = __ldcg(&abase[(c16 * 2 + mt) * 32 + lane]);
            a[mt][0] = v.x; a[mt][1] = v.y; a[mt][2] = v.z; a[mt][3] = v.w;
        }
#pragma unroll
        for (int mt = 0; mt < 2; ++mt) {
            mma_f16(acc + (mt * 4 + 0) * 4, a[mt], b0.x, b0.y);
            mma_f16(acc + (mt * 4 + 1) * 4, a[mt], b0.z, b0.w);
            mma_f16(acc + (mt * 4 + 2) * 4, a[mt], b1.x, b1.y);
            mma_f16(acc + (mt * 4 + 3) * 4, a[mt], b1.z, b1.w);
        }
    }
}

// ---- store warp's 32x32 partial into its red slab ----
__device__ __forceinline__ void sts_part(const float* acc, float* __restrict__ red,
                                         int wid, int g4, int l4) {
#pragma unroll
    for (int mt = 0; mt < 2; ++mt) {
#pragma unroll
        for (int nt = 0; nt < 4; ++nt) {
            const float* a = acc + (mt * 4 + nt) * 4;
            int row = mt * 16 + g4;
            int col = nt * 8 + 2 * l4;
            *(float2*)&red[wid * (32 * RED_S) + row * RED_S + col] = make_float2(a[0], a[1]);
            *(float2*)&red[wid * (32 * RED_S) + (row + 8) * RED_S + col] = make_float2(a[2], a[3]);
        }
    }
}

// ============ Fused persistent LSTM: accumulator-level fusion ===========
// All 16 warps on the critical path (R12 shape). Warp w owns concat-K rows
// x:[w*64,+64) AND h:[1024+w*64,+64); acc = x-part(t+1) (computed in the
// producer-skew window) + h-part(t+1) (after poll). One STS, 16-way reduce.
__global__ __launch_bounds__(NT2, 1) void lstm_fused(const float* __restrict__ Wfull,
                                                     const float* __restrict__ bias,
                                                     float* __restrict__ out) {
    extern __shared__ uint32_t dynsmem[];
    uint32_t* W_s = dynsmem;                          // 16 warps * 2048 words = 128KB
    float* red = (float*)(dynsmem + 32768);           // 16 * 32 * 40 floats = 80KB

    const int tid = threadIdx.x;
    const int wid = tid >> 5, lane = tid & 31;
    const int l4 = lane & 3, g4 = lane >> 2;
    const int bid = blockIdx.x;
    const int n0 = bid * 8;
    const int pb = (tid >> 3) & 31;
    const int pn = tid & 7;
    const bool active = tid < 256;

    // pointwise h-store address: element (b=pb, k=n0+pn), fragment layout (R12)
    const int hword = ((bid >> 1) * 2 + (pb >> 4)) * 128 + ((pb & 7) * 4 + (pn >> 1)) * 4 +
                      (bid & 1) * 2 + ((pb >> 3) & 1);
    const int hbyte = hword * 4 + (pn & 1) * 2;

    // ---- pack concat-W into SMEM: warp slab = [x sub-slab 1024w | h sub-slab 1024w] ----
    for (int widx = tid; widx < 32768; widx += NT2) {
        int w = widx >> 11, rem = widx & 2047;
        int s = rem >> 10, rem2 = rem & 1023;
        int kk = rem2 >> 8, q128 = (rem2 >> 7) & 1;
        int lw = (rem2 >> 2) & 31, low2 = rem2 & 3;
        int nt = q128 * 2 + (low2 >> 1), hi = low2 & 1;
        int g4c = lw >> 2, l4w = lw & 3;
        int k = s * 1024 + w * 64 + kk * 16 + hi * 8 + l4w * 2;   // concat row
        int col = nt * H_ + n0 + g4c;
        W_s[widx] = packh2(__ldg(Wfull + (size_t)k * ZN + col),
                           __ldg(Wfull + (size_t)(k + 1) * ZN + col));
    }

    float bz[4];
    if (active) {
#pragma unroll
        for (int g = 0; g < 4; ++g) bz[g] = __ldg(bias + g * H_ + n0 + pn);
    }
    __syncthreads();

    const uint4* Wqx = (const uint4*)W_s + (size_t)wid * 512;   // x sub-slab
    const uint4* Wqh = Wqx + 256;                                // h sub-slab
    const int c16b = wid * 4;
    float c_reg = 0.0f;

    // ---- prologue: partials for step 0 (h = 0 -> x part only) ----
    {
        float acc[32];
#pragma unroll
        for (int e = 0; e < 32; ++e) acc[e] = 0.0f;
        mma_part(acc, (const uint4*)g_xp, Wqx, c16b, lane);
        sts_part(acc, red, wid, g4, l4);
    }
    __syncthreads();

    for (int t = 0; t < T_ - 1; ++t) {
        // ---- gates for step t ----
        if (active) {
            float z[4];
#pragma unroll
            for (int g = 0; g < 4; ++g) {
                float s = bz[g];
#pragma unroll
                for (int w = 0; w < 16; ++w)
                    s += red[w * (32 * RED_S) + pb * RED_S + g * 8 + pn];
                z[g] = s;
            }
            c_reg = sigf(z[2] + 1.0f) * c_reg + sigf(z[0]) * tanhf(z[1]);
            float hv = sigf(z[3]) * tanhf(c_reg);
            unsigned short hs = __half_as_ushort(__float2half_rn(hv));
            asm volatile("st.global.cg.u16 [%0], %1;"
                         :: "l"((char*)g_h16[(t + 1) & 1] + hbyte), "h"(hs) : "memory");
        }
        __syncthreads();                       // h(t+1) stores done, red reads done
        if (tid == 0) st_rel(&g_flags[bid * 32], (unsigned)(t + 1));
        if (active) __stcs(&out[(size_t)pb * (T_ * H_) + (size_t)t * H_ + n0 + pn], c_reg);

        // ---- partials for step t+1: x-part (skew window), poll, h-part ----
        float acc[32];
#pragma unroll
        for (int e = 0; e < 32; ++e) acc[e] = 0.0f;
        mma_part(acc, (const uint4*)(g_xp + (size_t)(t + 1) * 16384), Wqx, c16b, lane);

        if (lane < 8) {
            const unsigned* fp = &g_flags[(wid * 8 + lane) * 32];
            while (ld_acq(fp) < (unsigned)(t + 1)) { }
        }
        __syncwarp();
        mma_part(acc, (const uint4*)g_h16[(t + 1) & 1], Wqh, c16b, lane);
        sts_part(acc, red, wid, g4, l4);
        __syncthreads();                       // partials for t+1 visible
    }

    // ---- epilogue: gates for step T-1 ----
    if (active) {
        float z[4];
#pragma unroll
        for (int g = 0; g < 4; ++g) {
            float s = bz[g];
#pragma unroll
            for (int w = 0; w < 16; ++w)
                s += red[w * (32 * RED_S) + pb * RED_S + g * 8 + pn];
            z[g] = s;
        }
        c_reg = sigf(z[2] + 1.0f) * c_reg + sigf(z[0]) * tanhf(z[1]);
        __stcs(&out[(size_t)pb * (T_ * H_) + (size_t)(T_ - 1) * H_ + n0 + pn], c_reg);
    }

    // ---- reset flags for deterministic graph replay ----
    __syncthreads();
    if (tid == 0) atomicAdd(&g_done, 1u);
    if (bid == 0) {
        if (tid == 0) {
            while (*(volatile unsigned*)&g_done < (unsigned)NBLK) { }
        }
        __syncthreads();
        if (tid < NBLK) g_flags[tid * 32] = 0u;
        __syncthreads();
        if (tid == 0) { __threadfence(); g_done = 0u; }
    }
}

// ---------------- launch ----------------
extern "C" void kernel_launch(void* const* d_in, const int* in_sizes, int n_in,
                              void* d_out, int out_size) {
    (void)in_sizes; (void)n_in; (void)out_size;
    const float* x    = (const float*)d_in[0];
    const float* kern = (const float*)d_in[2];
    const float* bias = (const float*)d_in[3];
    float* out = (float*)d_out;

    const int smem2 = (32768 + 16 * 32 * RED_S) * 4;   // 212992 B
    cudaFuncSetAttribute(lstm_fused, cudaFuncAttributeMaxDynamicSharedMemorySize, smem2);

    repack_x<<<T_, 256>>>(x);
    lstm_fused<<<NBLK, NT2, smem2>>>(kern, bias, out);
}